// round 9
// baseline (speedup 1.0000x reference)
#include <cuda_runtime.h>
#include <cuda_bf16.h>
#include <cstdint>

// Problem constants (shapes fixed by the dataset)
#define MAXN 100000
#define MAXE 3400000
#define F_IN 512
#define H1   256
#define H2   128
#define NCLS 4
#define NB_SCAN ((MAXN + 255) / 256)

// Scratch buffers: __device__ globals, float4-typed for 16B alignment.
__device__ float4 g_h1  [(size_t)MAXN * H1 / 4];
__device__ float4 g_agg1[(size_t)MAXN * H1 / 4];
__device__ float4 g_h2  [(size_t)MAXN * H2 / 4];
__device__ float  g_dinv[MAXN];
__device__ int    g_is64;   // 1 if edge_index is int64, 0 if int32

// CSR structures (rebuilt every call; deterministic up to neighbor order)
__device__ int g_csr_src[MAXE];
__device__ int g_row_ptr[MAXN + 1];
__device__ int g_row_cnt[MAXN];          // histogram, then scatter cursor
__device__ int g_blocksum[NB_SCAN + 1];

// Buffer-id -> device pointer resolution (host-side symbol lookup is
// unreliable in this harness; resolve on-device)
#define BUF_H1   0
#define BUF_AGG1 1
#define BUF_H2   2

__device__ __forceinline__ float* get_buf(int id) {
    switch (id) {
        case BUF_H1:   return reinterpret_cast<float*>(g_h1);
        case BUF_AGG1: return reinterpret_cast<float*>(g_agg1);
        default:       return reinterpret_cast<float*>(g_h2);
    }
}

// Load edge index element at logical position pos (0..2E-1), dtype-agnostic.
__device__ __forceinline__ int load_idx(const void* ei, long long pos) {
    if (g_is64) return (int)(reinterpret_cast<const long long*>(ei)[pos]);
    return reinterpret_cast<const int*>(ei)[pos];
}

// ---------------------------------------------------------------------------
// Dtype detection: int64 indices < 2^31 have all-zero odd 32-bit words.
// ---------------------------------------------------------------------------
__global__ void k_detect_init() { g_is64 = 1; }

__global__ void k_detect(const int* __restrict__ ei_words, int E2) {
    int i = blockIdx.x * blockDim.x + threadIdx.x;
    if (i >= 4096) return;
    long long w = 2LL * i + 1;
    if (w < E2 && ei_words[w] != 0) g_is64 = 0;
}

// ---------------------------------------------------------------------------
// CSR build: histogram -> exclusive scan -> scatter
// ---------------------------------------------------------------------------
__global__ void k_zero_cnt(int N) {
    int i = blockIdx.x * blockDim.x + threadIdx.x;
    if (i < N) g_row_cnt[i] = 0;
}

__global__ void k_hist(const void* __restrict__ ei, int E, int N) {
    int e = blockIdx.x * blockDim.x + threadIdx.x;
    if (e < E) {
        int d = load_idx(ei, (long long)E + e);
        if ((unsigned)d < (unsigned)N) atomicAdd(&g_row_cnt[d], 1);
    }
}

__global__ void k_dinv(int N) {
    int i = blockIdx.x * blockDim.x + threadIdx.x;
    if (i < N) g_dinv[i] = rsqrtf((float)g_row_cnt[i] + 1.0f);  // +1 self loop
}

// Per-block exclusive scan; block totals to g_blocksum.
__global__ void k_scan1(int N) {
    __shared__ int sh[256];
    const int t = threadIdx.x;
    const int i = blockIdx.x * 256 + t;
    int v = (i < N) ? g_row_cnt[i] : 0;
    sh[t] = v;
    __syncthreads();
    #pragma unroll
    for (int off = 1; off < 256; off <<= 1) {
        int x = (t >= off) ? sh[t - off] : 0;
        __syncthreads();
        sh[t] += x;
        __syncthreads();
    }
    if (i < N) g_row_ptr[i] = sh[t] - v;
    if (t == 255) g_blocksum[blockIdx.x] = sh[255];
}

__global__ void k_scan2(int nb) {
    __shared__ int sh[1024];
    const int t = threadIdx.x;
    int v = (t < nb) ? g_blocksum[t] : 0;
    sh[t] = v;
    __syncthreads();
    #pragma unroll
    for (int off = 1; off < 1024; off <<= 1) {
        int x = (t >= off) ? sh[t - off] : 0;
        __syncthreads();
        sh[t] += x;
        __syncthreads();
    }
    if (t < nb) g_blocksum[t] = sh[t] - v;
}

__global__ void k_scan3(int N) {
    const int i = blockIdx.x * 256 + threadIdx.x;
    if (i < N) {
        g_row_ptr[i] += g_blocksum[i >> 8];
        if (i == N - 1) g_row_ptr[N] = g_row_ptr[i] + g_row_cnt[i];
    }
}

__global__ void k_scatter(const void* __restrict__ ei, int E, int N) {
    int e = blockIdx.x * blockDim.x + threadIdx.x;
    if (e >= E) return;
    int s = load_idx(ei, e);
    int d = load_idx(ei, (long long)E + e);
    if ((unsigned)s >= (unsigned)N || (unsigned)d >= (unsigned)N) return;
    int pos = g_row_ptr[d] + atomicAdd(&g_row_cnt[d], 1);
    if (pos < MAXE) g_csr_src[pos] = s;
}

// ---------------------------------------------------------------------------
// Tensor-core GEMM with 3-term bf16 split (near-fp32 accuracy):
//   a*b ~= ahi*bhi + ahi*blo + alo*bhi   (alo*blo ~ 2^-18, omitted)
// C[N,M] = A[N,K] @ B[K,M].  BM=128, BN=128, BK=32, 256 threads.
// Warp tile 32x64 (2 m-tiles x 8 n-tiles of m16n8k16).
// ---------------------------------------------------------------------------
#define SMA_STRIDE 40   // 32 data + 8 pad bf16 -> conflict-free lds.b32 frags

__device__ __forceinline__ void bf16_split(float v, __nv_bfloat16& hi, __nv_bfloat16& lo) {
    hi = __float2bfloat16_rn(v);
    lo = __float2bfloat16_rn(v - __bfloat162float(hi));
}

__device__ __forceinline__ void mma16816(float* c, const uint32_t* a, const uint32_t* b) {
    asm volatile(
        "mma.sync.aligned.m16n8k16.row.col.f32.bf16.bf16.f32 "
        "{%0,%1,%2,%3},{%4,%5,%6,%7},{%8,%9},{%0,%1,%2,%3};"
        : "+f"(c[0]), "+f"(c[1]), "+f"(c[2]), "+f"(c[3])
        : "r"(a[0]), "r"(a[1]), "r"(a[2]), "r"(a[3]), "r"(b[0]), "r"(b[1]));
}

__global__ void __launch_bounds__(256) k_gemm_tc(const float* __restrict__ Aext,
                                                 int a_id,
                                                 const float* __restrict__ B,
                                                 int c_id,
                                                 int Nrows, int K, int M) {
    const float* A = (a_id < 0) ? Aext : get_buf(a_id);
    float*       C = get_buf(c_id);

    // [hi=0 / lo=1]; A: [m][k] (row-major), B: [n][k] (transposed in smem)
    __shared__ __nv_bfloat16 sA[2][128 * SMA_STRIDE];
    __shared__ __nv_bfloat16 sB[2][128 * SMA_STRIDE];

    const int tid  = threadIdx.x;
    const int wid  = tid >> 5;
    const int lane = tid & 31;
    const int g    = lane >> 2;    // group id 0..7
    const int tg   = lane & 3;     // thread-in-group 0..3
    const int wm   = wid & 3;      // warp m index (0..3) -> rows wm*32
    const int wn   = wid >> 2;     // warp n index (0..1) -> cols wn*64
    const int row0 = blockIdx.y * 128;
    const int col0 = blockIdx.x * 128;

    float acc[2][8][4];
    #pragma unroll
    for (int mt = 0; mt < 2; mt++)
        #pragma unroll
        for (int nt = 0; nt < 8; nt++)
            #pragma unroll
            for (int r = 0; r < 4; r++) acc[mt][nt][r] = 0.f;

    for (int k0 = 0; k0 < K; k0 += 32) {
        // ---- Load + split A tile: 128 x 32 fp32 -> sA hi/lo ----
        #pragma unroll
        for (int it = 0; it < 4; it++) {
            const int idx = tid + it * 256;         // 0..1023
            const int m   = idx >> 3;               // 0..127
            const int kq  = (idx & 7) << 2;         // 0,4,...,28
            const int gr  = row0 + m;
            float4 v = make_float4(0.f, 0.f, 0.f, 0.f);
            if (gr < Nrows)
                v = *reinterpret_cast<const float4*>(&A[(size_t)gr * K + k0 + kq]);
            float vs[4] = {v.x, v.y, v.z, v.w};
            #pragma unroll
            for (int j = 0; j < 4; j += 2) {
                __nv_bfloat16 h0, l0, h1, l1;
                bf16_split(vs[j],     h0, l0);
                bf16_split(vs[j + 1], h1, l1);
                *reinterpret_cast<__nv_bfloat162*>(&sA[0][m * SMA_STRIDE + kq + j]) =
                    __halves2bfloat162(h0, h1);
                *reinterpret_cast<__nv_bfloat162*>(&sA[1][m * SMA_STRIDE + kq + j]) =
                    __halves2bfloat162(l0, l1);
            }
        }
        // ---- Load + split B tile: 32 x 128 fp32, store transposed [n][k] ----
        #pragma unroll
        for (int it = 0; it < 4; it++) {
            const int idx = tid + it * 256;
            const int k   = idx >> 5;               // 0..31
            const int nq  = (idx & 31) << 2;        // 0,4,...,124
            float4 v = *reinterpret_cast<const float4*>(&B[(size_t)(k0 + k) * M + col0 + nq]);
            float vs[4] = {v.x, v.y, v.z, v.w};
            #pragma unroll
            for (int j = 0; j < 4; j++) {
                __nv_bfloat16 h, l;
                bf16_split(vs[j], h, l);
                sB[0][(nq + j) * SMA_STRIDE + k] = h;
                sB[1][(nq + j) * SMA_STRIDE + k] = l;
            }
        }
        __syncthreads();

        // ---- Compute: 2 k16 steps ----
        #pragma unroll
        for (int ks = 0; ks < 2; ks++) {
            const int kb = ks * 16;

            uint32_t ah[2][4], al[2][4];
            #pragma unroll
            for (int mt = 0; mt < 2; mt++) {
                const int m = wm * 32 + mt * 16 + g;
                const int o0 = m * SMA_STRIDE + kb + 2 * tg;
                const int o1 = (m + 8) * SMA_STRIDE + kb + 2 * tg;
                ah[mt][0] = *reinterpret_cast<const uint32_t*>(&sA[0][o0]);
                ah[mt][1] = *reinterpret_cast<const uint32_t*>(&sA[0][o1]);
                ah[mt][2] = *reinterpret_cast<const uint32_t*>(&sA[0][o0 + 8]);
                ah[mt][3] = *reinterpret_cast<const uint32_t*>(&sA[0][o1 + 8]);
                al[mt][0] = *reinterpret_cast<const uint32_t*>(&sA[1][o0]);
                al[mt][1] = *reinterpret_cast<const uint32_t*>(&sA[1][o1]);
                al[mt][2] = *reinterpret_cast<const uint32_t*>(&sA[1][o0 + 8]);
                al[mt][3] = *reinterpret_cast<const uint32_t*>(&sA[1][o1 + 8]);
            }
            uint32_t bh[8][2], bl[8][2];
            #pragma unroll
            for (int nt = 0; nt < 8; nt++) {
                const int n = wn * 64 + nt * 8 + g;
                const int o = n * SMA_STRIDE + kb + 2 * tg;
                bh[nt][0] = *reinterpret_cast<const uint32_t*>(&sB[0][o]);
                bh[nt][1] = *reinterpret_cast<const uint32_t*>(&sB[0][o + 8]);
                bl[nt][0] = *reinterpret_cast<const uint32_t*>(&sB[1][o]);
                bl[nt][1] = *reinterpret_cast<const uint32_t*>(&sB[1][o + 8]);
            }

            #pragma unroll
            for (int mt = 0; mt < 2; mt++)
                #pragma unroll
                for (int nt = 0; nt < 8; nt++) {
                    mma16816(acc[mt][nt], ah[mt], bh[nt]);
                    mma16816(acc[mt][nt], ah[mt], bl[nt]);
                    mma16816(acc[mt][nt], al[mt], bh[nt]);
                }
        }
        __syncthreads();
    }

    // ---- Epilogue: store fp32 C ----
    #pragma unroll
    for (int mt = 0; mt < 2; mt++) {
        #pragma unroll
        for (int nt = 0; nt < 8; nt++) {
            const int gc  = col0 + wn * 64 + nt * 8 + 2 * tg;
            const int gr0 = row0 + wm * 32 + mt * 16 + g;
            if (gr0 < Nrows) {
                float2 v = make_float2(acc[mt][nt][0], acc[mt][nt][1]);
                *reinterpret_cast<float2*>(&C[(size_t)gr0 * M + gc]) = v;
            }
            const int gr1 = gr0 + 8;
            if (gr1 < Nrows) {
                float2 v = make_float2(acc[mt][nt][2], acc[mt][nt][3]);
                *reinterpret_cast<float2*>(&C[(size_t)gr1 * M + gc]) = v;
            }
        }
    }
}

// ---------------------------------------------------------------------------
// CSR aggregation, one warp per dst node, fused self-loop + bias + ReLU:
//   out[d] = relu( dd * ( dd*h[d] + sum_s dinv[s]*h[s] ) + bias )
// ---------------------------------------------------------------------------
template <int H>
__global__ void __launch_bounds__(256) k_agg_csr(int h_id, int out_id,
                                                 const float* __restrict__ bias,
                                                 int N) {
    const float* h   = get_buf(h_id);
    float*       out = get_buf(out_id);

    const int d    = (int)((blockIdx.x * (unsigned)blockDim.x + threadIdx.x) >> 5);
    const int lane = threadIdx.x & 31;
    if (d >= N) return;

    constexpr int C = H / 128;
    const float dd = g_dinv[d];

    float4 acc[C];
    {
        const float4* hd = reinterpret_cast<const float4*>(h + (size_t)d * H);
        #pragma unroll
        for (int c = 0; c < C; c++) {
            float4 v = hd[lane + 32 * c];
            acc[c] = make_float4(v.x * dd, v.y * dd, v.z * dd, v.w * dd);
        }
    }

    const int beg = g_row_ptr[d];
    const int end = g_row_ptr[d + 1];

    for (int j0 = beg; j0 < end; j0 += 32) {
        const int myidx = (j0 + lane < end) ? g_csr_src[j0 + lane] : 0;
        const int cnt   = min(32, end - j0);
        for (int k = 0; k < cnt; k++) {
            const int   s = __shfl_sync(0xffffffffu, myidx, k);
            const float w = g_dinv[s];
            const float4* hs = reinterpret_cast<const float4*>(h + (size_t)s * H);
            #pragma unroll
            for (int c = 0; c < C; c++) {
                float4 v = hs[lane + 32 * c];
                acc[c].x = fmaf(v.x, w, acc[c].x);
                acc[c].y = fmaf(v.y, w, acc[c].y);
                acc[c].z = fmaf(v.z, w, acc[c].z);
                acc[c].w = fmaf(v.w, w, acc[c].w);
            }
        }
    }

    const float4* bb = reinterpret_cast<const float4*>(bias);
    #pragma unroll
    for (int c = 0; c < C; c++) {
        float4 b = bb[lane + 32 * c];
        float4 r;
        r.x = fmaxf(fmaf(acc[c].x, dd, b.x), 0.f);
        r.y = fmaxf(fmaf(acc[c].y, dd, b.y), 0.f);
        r.z = fmaxf(fmaf(acc[c].z, dd, b.z), 0.f);
        r.w = fmaxf(fmaf(acc[c].w, dd, b.w), 0.f);
        reinterpret_cast<float4*>(out + (size_t)d * H)[lane + 32 * c] = r;
    }
}

// ---------------------------------------------------------------------------
// Layer-2 aggregation fused with bias + relu + logits + log_softmax.
// ---------------------------------------------------------------------------
__global__ void __launch_bounds__(256) k_agg_csr_final(int h_id,
                                                       const float* __restrict__ bias,
                                                       const float* __restrict__ Wl,
                                                       const float* __restrict__ bl,
                                                       float* __restrict__ out,
                                                       int N) {
    const float* h = get_buf(h_id);

    const int d    = (int)((blockIdx.x * (unsigned)blockDim.x + threadIdx.x) >> 5);
    const int lane = threadIdx.x & 31;
    if (d >= N) return;

    const float dd = g_dinv[d];

    float4 acc;
    {
        float4 v = reinterpret_cast<const float4*>(h + (size_t)d * H2)[lane];
        acc = make_float4(v.x * dd, v.y * dd, v.z * dd, v.w * dd);
    }

    const int beg = g_row_ptr[d];
    const int end = g_row_ptr[d + 1];

    for (int j0 = beg; j0 < end; j0 += 32) {
        const int myidx = (j0 + lane < end) ? g_csr_src[j0 + lane] : 0;
        const int cnt   = min(32, end - j0);
        for (int k = 0; k < cnt; k++) {
            const int   s = __shfl_sync(0xffffffffu, myidx, k);
            const float w = g_dinv[s];
            float4 v = reinterpret_cast<const float4*>(h + (size_t)s * H2)[lane];
            acc.x = fmaf(v.x, w, acc.x);
            acc.y = fmaf(v.y, w, acc.y);
            acc.z = fmaf(v.z, w, acc.z);
            acc.w = fmaf(v.w, w, acc.w);
        }
    }

    float4 b = reinterpret_cast<const float4*>(bias)[lane];
    float r0 = fmaxf(fmaf(acc.x, dd, b.x), 0.f);
    float r1 = fmaxf(fmaf(acc.y, dd, b.y), 0.f);
    float r2 = fmaxf(fmaf(acc.z, dd, b.z), 0.f);
    float r3 = fmaxf(fmaf(acc.w, dd, b.w), 0.f);

    const float4 w0 = reinterpret_cast<const float4*>(Wl)[lane * 4 + 0];
    const float4 w1 = reinterpret_cast<const float4*>(Wl)[lane * 4 + 1];
    const float4 w2 = reinterpret_cast<const float4*>(Wl)[lane * 4 + 2];
    const float4 w3 = reinterpret_cast<const float4*>(Wl)[lane * 4 + 3];
    float l0 = r0 * w0.x + r1 * w1.x + r2 * w2.x + r3 * w3.x;
    float l1 = r0 * w0.y + r1 * w1.y + r2 * w2.y + r3 * w3.y;
    float l2 = r0 * w0.z + r1 * w1.z + r2 * w2.z + r3 * w3.z;
    float l3 = r0 * w0.w + r1 * w1.w + r2 * w2.w + r3 * w3.w;

    #pragma unroll
    for (int off = 16; off > 0; off >>= 1) {
        l0 += __shfl_xor_sync(0xffffffffu, l0, off);
        l1 += __shfl_xor_sync(0xffffffffu, l1, off);
        l2 += __shfl_xor_sync(0xffffffffu, l2, off);
        l3 += __shfl_xor_sync(0xffffffffu, l3, off);
    }

    if (lane == 0) {
        l0 += bl[0]; l1 += bl[1]; l2 += bl[2]; l3 += bl[3];
        float m = fmaxf(fmaxf(l0, l1), fmaxf(l2, l3));
        float e0 = __expf(l0 - m), e1 = __expf(l1 - m),
              e2 = __expf(l2 - m), e3 = __expf(l3 - m);
        float lse = logf(e0 + e1 + e2 + e3);
        float4 r = make_float4(l0 - m - lse, l1 - m - lse, l2 - m - lse, l3 - m - lse);
        *reinterpret_cast<float4*>(&out[(size_t)d * NCLS]) = r;
    }
}

// ---------------------------------------------------------------------------
// Launch
// ---------------------------------------------------------------------------
extern "C" void kernel_launch(void* const* d_in, const int* in_sizes, int n_in,
                              void* d_out, int out_size) {
    const float* x   = (const float*)d_in[0];
    const void*  ei  = d_in[1];
    const float* W1  = (const float*)d_in[2];
    const float* b1  = (const float*)d_in[3];
    const float* W2  = (const float*)d_in[4];
    const float* b2  = (const float*)d_in[5];
    const float* Wl  = (const float*)d_in[6];
    const float* bl  = (const float*)d_in[7];
    float*       out = (float*)d_out;

    const int N = in_sizes[0] / F_IN;
    const int E = in_sizes[1] / 2;
    const int T = 256;
    const int nb = (N + 255) / 256;

    // Detect edge_index dtype (int32 vs int64)
    k_detect_init<<<1, 1>>>();
    k_detect<<<(4096 + T - 1) / T, T>>>((const int*)ei, 2 * E);

    // CSR build + degree normalization
    k_zero_cnt<<<nb, T>>>(N);
    k_hist<<<(E + T - 1) / T, T>>>(ei, E, N);
    k_dinv<<<nb, T>>>(N);
    k_scan1<<<nb, T>>>(N);
    k_scan2<<<1, 1024>>>(nb);
    k_scan3<<<nb, T>>>(N);
    k_zero_cnt<<<nb, T>>>(N);
    k_scatter<<<(E + T - 1) / T, T>>>(ei, E, N);

    // Layer 1: h1 = x @ W1 (tensor core); agg fused with self-loop+bias+relu
    {
        dim3 grid(H1 / 128, (N + 127) / 128);
        k_gemm_tc<<<grid, 256>>>(x, -1, W1, BUF_H1, N, F_IN, H1);
    }
    k_agg_csr<H1><<<(int)(((long long)N * 32 + T - 1) / T), T>>>(BUF_H1, BUF_AGG1, b1, N);

    // Layer 2: h2 = relu1 @ W2 (tensor core); agg fused with logits+softmax
    {
        dim3 grid(H2 / 128, (N + 127) / 128);
        k_gemm_tc<<<grid, 256>>>(nullptr, BUF_AGG1, W2, BUF_H2, N, H1, H2);
    }
    k_agg_csr_final<<<(int)(((long long)N * 32 + T - 1) / T), T>>>(BUF_H2, b2, Wl, bl, out, N);
}